// round 9
// baseline (speedup 1.0000x reference)
#include <cuda_runtime.h>
#include <cuda_fp16.h>
#include <cstdint>

// ============================================================================
// out_i = || P * U(params) * s_i ||^2, 131072 states of dim 256.
// params batch-invariant -> precompute A = P*U (128x256 complex), then a real
// fp16 mma.sync GEMM (tcgen05 unavailable on compute_103 base target):
//   S = [sr | si] (131072 x 512 fp32 -> fp16 on the fly)
//   Wh[n][k] fp16 (256 x 512), n<128: [Ar | -Ai], n>=128: [Ai | Ar]
//   C[m][n] = sum_k S[m][k] Wh[n][k];  out_m = sum_n C[m][n]^2
//
// R9: rate-hypothesis test. Evidence: R3/R6/R8 (three different pipelines)
//     all converge to ~115-120us = exactly the wall predicted if
//     HMMA.16816 fp32-acc has rt=16cyc/SMSP (half rate). This round switches
//     the inner accumulation to f16 (predicted rt=8cyc/SMSP), promoting to
//     f32 master accumulators after every K=64 chunk (4 MMAs of f16 acc ->
//     bounded rounding error, est rel_err ~1e-4). Structure = R6 (best).
// ============================================================================

#define NLAYERS 3
#define NQ 8

__device__ __half Wh_global[256 * 512];

// ---------------------------------------------------------------------------
__device__ __forceinline__ uint32_t smem_u32(const void* p) {
    uint32_t a;
    asm("{ .reg .u64 t; cvta.to.shared.u64 t, %1; cvt.u32.u64 %0, t; }"
        : "=r"(a) : "l"(p));
    return a;
}

__device__ __forceinline__ void ldmatrix_x4(uint32_t r[4], uint32_t addr) {
    asm volatile("ldmatrix.sync.aligned.m8n8.x4.shared.b16 {%0,%1,%2,%3}, [%4];"
                 : "=r"(r[0]), "=r"(r[1]), "=r"(r[2]), "=r"(r[3]) : "r"(addr));
}

// f16-accumulate MMA: D (f16x2 in 2 regs) = A*B + C
__device__ __forceinline__ void mma16816_f16(uint32_t c[2], const uint32_t a[4],
                                             uint32_t b0, uint32_t b1) {
    asm volatile(
        "mma.sync.aligned.m16n8k16.row.col.f16.f16.f16.f16 "
        "{%0,%1}, {%2,%3,%4,%5}, {%6,%7}, {%0,%1};"
        : "+r"(c[0]), "+r"(c[1])
        : "r"(a[0]), "r"(a[1]), "r"(a[2]), "r"(a[3]), "r"(b0), "r"(b1));
}

__device__ __forceinline__ void cp_async16(uint32_t dst, const void* src) {
    asm volatile("cp.async.cg.shared.global [%0], [%1], 16;"
                 :: "r"(dst), "l"(src) : "memory");
}
#define CP_COMMIT() asm volatile("cp.async.commit_group;" ::: "memory")
#define CP_WAIT(n)  asm volatile("cp.async.wait_group %0;" :: "n"(n) : "memory")

// ---------------------------------------------------------------------------
// Setup: block k simulates basis state |k> (gates from smem, trig once).
// ---------------------------------------------------------------------------
__global__ void build_weights_kernel(const float* __restrict__ params) {
    __shared__ float2 st[256];
    __shared__ float g[NLAYERS * NQ][8];
    int k = blockIdx.x;
    int t = threadIdx.x;

    if (t < NLAYERS * NQ) {
        const float* pr = params + t * 3;
        float hx = 0.5f * pr[0], hy = 0.5f * pr[1], hz = 0.5f * pr[2];
        float cx = cosf(hx), sx = sinf(hx);
        float cy = cosf(hy), sy = sinf(hy);
        float cz = cosf(hz), sz = sinf(hz);
        float m00r =  cy * cx, m00i =  sy * sx;
        float m01r = -sy * cx, m01i = -cy * sx;
        float m10r =  sy * cx, m10i = -cy * sx;
        float m11r =  cy * cx, m11i = -sy * sx;
        g[t][0] = cz * m00r + sz * m00i;  g[t][1] = cz * m00i - sz * m00r;
        g[t][2] = cz * m01r + sz * m01i;  g[t][3] = cz * m01i - sz * m01r;
        g[t][4] = cz * m10r - sz * m10i;  g[t][5] = cz * m10i + sz * m10r;
        g[t][6] = cz * m11r - sz * m11i;  g[t][7] = cz * m11i + sz * m11r;
    }
    st[t] = make_float2(t == k ? 1.0f : 0.0f, 0.0f);
    __syncthreads();

    for (int l = 0; l < NLAYERS; l++) {
        for (int q = 0; q < NQ; q++) {
            const float* u = g[l * NQ + q];
            float u00r = u[0], u00i = u[1], u01r = u[2], u01i = u[3];
            float u10r = u[4], u10i = u[5], u11r = u[6], u11i = u[7];
            int p = 7 - q;  // qubit 0 = MSB of flat index
            if (t < 128) {
                int lo = t & ((1 << p) - 1);
                int i0 = ((t >> p) << (p + 1)) | lo;
                int i1 = i0 | (1 << p);
                float2 a0 = st[i0], a1 = st[i1];
                float2 n0, n1;
                n0.x = u00r*a0.x - u00i*a0.y + u01r*a1.x - u01i*a1.y;
                n0.y = u00r*a0.y + u00i*a0.x + u01r*a1.y + u01i*a1.x;
                n1.x = u10r*a0.x - u10i*a0.y + u11r*a1.x - u11i*a1.y;
                n1.y = u10r*a0.y + u10i*a0.x + u11r*a1.y + u11i*a1.x;
                st[i0] = n0;
                st[i1] = n1;
            }
            __syncthreads();
        }
        for (int q = 0; q < NQ; q++) {
            int pc = 7 - q;
            int pt = 7 - ((q + 1) & 7);
            if (((t >> pc) & 1) == 1 && ((t >> pt) & 1) == 0) {
                int j = t | (1 << pt);
                float2 tmp = st[t];
                st[t] = st[j];
                st[j] = tmp;
            }
            __syncthreads();
        }
    }
    if (t < 128) {
        float re = st[t].x, im = st[t].y;
        Wh_global[t * 512 + k]               = __float2half_rn(re);
        Wh_global[t * 512 + 256 + k]         = __float2half_rn(-im);
        Wh_global[(128 + t) * 512 + k]       = __float2half_rn(im);
        Wh_global[(128 + t) * 512 + 256 + k] = __float2half_rn(re);
    }
}

// ---------------------------------------------------------------------------
// GEMM: CTA = 128 rows x 256 N, 256 threads = 8 warps, warp grid 2(M) x 4(N),
// warp tile 64x64. K = 512 in 8 chunks of 64. f16 accumulation within each
// chunk (hacc), promoted to f32 master (acc) per chunk.
// SMEM: A fp16 128x64 = 16KB x 2 stages at 0;  B fp16 256x64 = 32KB x 4
// stages at 32KB; red[128] at 160KB. 1 CTA/SM.
// ---------------------------------------------------------------------------
static constexpr uint32_t SA_STAGE = 16 * 1024;
static constexpr uint32_t SB_OFF   = 32 * 1024;
static constexpr uint32_t SB_STAGE = 32 * 1024;
static constexpr uint32_t RED_OFF  = 160 * 1024;
static constexpr uint32_t DYN_SMEM = 160 * 1024 + 512 + 1024;

__global__ void __launch_bounds__(256, 1)
qmm_kernel(const float* __restrict__ sre, const float* __restrict__ sim,
           float* __restrict__ out) {
    extern __shared__ char smem_raw[];
    uint32_t base  = smem_u32(smem_raw);
    uint32_t abase = (base + 1023u) & ~1023u;
    char* a = smem_raw + (abase - base);
    float* red = (float*)(a + RED_OFF);

    const int tid  = threadIdx.x;
    const int wid  = tid >> 5;
    const int lane = tid & 31;
    const int wm   = wid >> 2;  // 0..1 : rows wm*64..+63
    const int wn   = wid & 3;   // 0..3 : cols wn*64..+63

    // ldmatrix per-lane geometry
    const int r  = lane & 7;
    const int q  = lane >> 3;
    const uint32_t xorv = (uint32_t)r << 4;
    const uint32_t ch16 = (uint32_t)(q >> 1) << 4;
    const int rl = ((q & 1) << 3) + r;

    uint32_t aRow[4], bRow[4];
    #pragma unroll
    for (int mf = 0; mf < 4; mf++)
        aRow[mf] = abase + (uint32_t)(wm * 64 + mf * 16 + rl) * 128;
    #pragma unroll
    for (int nb = 0; nb < 4; nb++)
        bRow[nb] = abase + SB_OFF + (uint32_t)(wn * 64 + nb * 16 + rl) * 128;

    const long tileBase = (long)blockIdx.x * 128;

    float acc[4][8][4];        // f32 master
    #pragma unroll
    for (int mf = 0; mf < 4; mf++)
        #pragma unroll
        for (int nf = 0; nf < 8; nf++)
            #pragma unroll
            for (int i = 0; i < 4; i++) acc[mf][nf][i] = 0.0f;

    float4 av[8];

    // ---- prologue ----
    {
        #pragma unroll
        for (int it = 0; it < 8; it++) {
            int i = tid + it * 256;
            int row = i >> 4, f4 = i & 15;
            av[it] = *(const float4*)(sre + (tileBase + row) * 256 + f4 * 4);
        }
        #pragma unroll
        for (int cc = 0; cc < 2; cc++) {
            uint32_t sb = abase + SB_OFF + (uint32_t)cc * SB_STAGE;
            #pragma unroll
            for (int it = 0; it < 8; it++) {
                int i = tid + it * 256;
                int n = i >> 3, seg = i & 7;
                uint32_t dst = sb + (uint32_t)n * 128 +
                               (((uint32_t)seg * 16) ^ (((uint32_t)n & 7) << 4));
                cp_async16(dst, Wh_global + n * 512 + cc * 64 + seg * 8);
            }
            CP_COMMIT();
        }
    }

    for (int c = 0; c < 8; c++) {
        const uint32_t saoff = (uint32_t)(c & 1) * SA_STAGE;
        const uint32_t sboff = (uint32_t)(c & 3) * SB_STAGE;

        // store A(c) regs -> smem, fp32 -> fp16
        #pragma unroll
        for (int it = 0; it < 8; it++) {
            int i = tid + it * 256;
            int row = i >> 4, f4 = i & 15;
            __half2 p0 = __floats2half2_rn(av[it].x, av[it].y);
            __half2 p1 = __floats2half2_rn(av[it].z, av[it].w);
            uint2 u;
            u.x = *(const uint32_t*)&p0;
            u.y = *(const uint32_t*)&p1;
            uint32_t byte = (uint32_t)row * 128 +
                            (((uint32_t)f4 * 8) ^ (((uint32_t)row & 7) << 4));
            *(uint2*)(a + saoff + byte) = u;
        }

        // issue B(c+2) into stage (c+2)&3 (dummy commit keeps counts uniform)
        if (c + 2 < 8) {
            uint32_t sb = abase + SB_OFF + (uint32_t)((c + 2) & 3) * SB_STAGE;
            #pragma unroll
            for (int it = 0; it < 8; it++) {
                int i = tid + it * 256;
                int n = i >> 3, seg = i & 7;
                uint32_t dst = sb + (uint32_t)n * 128 +
                               (((uint32_t)seg * 16) ^ (((uint32_t)n & 7) << 4));
                cp_async16(dst, Wh_global + n * 512 + (c + 2) * 64 + seg * 8);
            }
        }
        CP_COMMIT();

        // prefetch A(c+1) into regs
        if (c < 7) {
            const int cn = c + 1;
            const float* src = (cn < 4) ? sre : sim;
            int cb = (cn & 3) * 64;
            #pragma unroll
            for (int it = 0; it < 8; it++) {
                int i = tid + it * 256;
                int row = i >> 4, f4 = i & 15;
                av[it] = *(const float4*)(src + (tileBase + row) * 256 + cb + f4 * 4);
            }
        }

        CP_WAIT(2);           // groups <= c complete
        __syncthreads();      // A(c) stores + B(c) visible to all warps

        // f16 chunk accumulators (zeroed each chunk)
        uint32_t hacc[4][8][2];
        #pragma unroll
        for (int mf = 0; mf < 4; mf++)
            #pragma unroll
            for (int nf = 0; nf < 8; nf++) {
                hacc[mf][nf][0] = 0u;
                hacc[mf][nf][1] = 0u;
            }

        // compute chunk c: 4 k-steps of 16, f16 accumulation
        #pragma unroll
        for (int ks = 0; ks < 4; ks++) {
            uint32_t cx = (((uint32_t)ks * 32) | ch16) ^ xorv;
            uint32_t af[4][4];
            #pragma unroll
            for (int mf = 0; mf < 4; mf++)
                ldmatrix_x4(af[mf], aRow[mf] + saoff + cx);
            uint32_t bf[4][4];
            #pragma unroll
            for (int nb = 0; nb < 4; nb++)
                ldmatrix_x4(bf[nb], bRow[nb] + sboff + cx);
            #pragma unroll
            for (int mf = 0; mf < 4; mf++)
                #pragma unroll
                for (int nf = 0; nf < 8; nf++) {
                    int nb = nf >> 1, sub = nf & 1;
                    mma16816_f16(hacc[mf][nf], af[mf], bf[nb][sub], bf[nb][sub + 2]);
                }
        }

        // promote chunk result into f32 master
        #pragma unroll
        for (int mf = 0; mf < 4; mf++)
            #pragma unroll
            for (int nf = 0; nf < 8; nf++) {
                float2 lo = __half22float2(*(const __half2*)&hacc[mf][nf][0]);
                float2 hi = __half22float2(*(const __half2*)&hacc[mf][nf][1]);
                acc[mf][nf][0] += lo.x;
                acc[mf][nf][1] += lo.y;
                acc[mf][nf][2] += hi.x;
                acc[mf][nf][3] += hi.y;
            }
    }

    // ---- epilogue: out[m] = sum_n C[m][n]^2 ----
    __syncthreads();
    if (tid < 128) red[tid] = 0.0f;
    __syncthreads();

    #pragma unroll
    for (int mf = 0; mf < 4; mf++) {
        float s_lo = 0.0f, s_hi = 0.0f;
        #pragma unroll
        for (int nf = 0; nf < 8; nf++) {
            s_lo = fmaf(acc[mf][nf][0], acc[mf][nf][0], s_lo);
            s_lo = fmaf(acc[mf][nf][1], acc[mf][nf][1], s_lo);
            s_hi = fmaf(acc[mf][nf][2], acc[mf][nf][2], s_hi);
            s_hi = fmaf(acc[mf][nf][3], acc[mf][nf][3], s_hi);
        }
        s_lo += __shfl_xor_sync(0xFFFFFFFF, s_lo, 1);
        s_lo += __shfl_xor_sync(0xFFFFFFFF, s_lo, 2);
        s_hi += __shfl_xor_sync(0xFFFFFFFF, s_hi, 1);
        s_hi += __shfl_xor_sync(0xFFFFFFFF, s_hi, 2);
        if ((lane & 3) == 0) {
            int row = wm * 64 + mf * 16 + (lane >> 2);
            atomicAdd(red + row, s_lo);
            atomicAdd(red + row + 8, s_hi);
        }
    }
    __syncthreads();
    if (tid < 128) out[tileBase + tid] = red[tid];
}

// ---------------------------------------------------------------------------
extern "C" void kernel_launch(void* const* d_in, const int* in_sizes, int n_in,
                              void* d_out, int out_size) {
    const float* params = (const float*)d_in[0];
    const float* sre    = (const float*)d_in[1];
    const float* sim    = (const float*)d_in[2];
    float* out = (float*)d_out;

    cudaFuncSetAttribute(qmm_kernel, cudaFuncAttributeMaxDynamicSharedMemorySize,
                         DYN_SMEM);

    build_weights_kernel<<<256, 256>>>(params);
    qmm_kernel<<<1024, 256, DYN_SMEM>>>(sre, sim, out);
}

// round 10
// speedup vs baseline: 1.2615x; 1.2615x over previous
#include <cuda_runtime.h>
#include <cuda_fp16.h>
#include <cstdint>

// ============================================================================
// out_i = || P * U(params) * s_i ||^2, 131072 states of dim 256.
// params batch-invariant -> precompute A = P*U (128x256 complex).
// R10: Gauss/Karatsuba 3M complex GEMM (25% fewer MMAs than the real-ified
//      form; R3/R6/R8 proved we sit exactly on the HMMA issue-rate wall,
//      and R9 proved f16-acc does not raise that rate).
//   For weight w = c+di and state s = a+bi:
//     k1 = (a+b)c, k2 = a(d-c), k3 = b(c+d);  Re = k1-k3, Im = k1+k2
//   Three fp16 GEMM planes, each (131072x256)x(256x128), fp32 accum:
//     plane0: Ssum x Wk1(=c),  plane1: Sr x Wk2(=d-c),  plane2: Si x Wk3(=c+d)
//   out_m = sum_n Re^2 + Im^2.
// ============================================================================

#define NLAYERS 3
#define NQ 8

// Wg[op][n][k]: op0 = Ar, op1 = Ai - Ar, op2 = Ar + Ai.  (128 n x 256 k each)
__device__ __half Wg_global[3 * 128 * 256];

// ---------------------------------------------------------------------------
__device__ __forceinline__ uint32_t smem_u32(const void* p) {
    uint32_t a;
    asm("{ .reg .u64 t; cvta.to.shared.u64 t, %1; cvt.u32.u64 %0, t; }"
        : "=r"(a) : "l"(p));
    return a;
}

__device__ __forceinline__ void ldmatrix_x4(uint32_t r[4], uint32_t addr) {
    asm volatile("ldmatrix.sync.aligned.m8n8.x4.shared.b16 {%0,%1,%2,%3}, [%4];"
                 : "=r"(r[0]), "=r"(r[1]), "=r"(r[2]), "=r"(r[3]) : "r"(addr));
}

__device__ __forceinline__ void mma16816(float c[4], const uint32_t a[4],
                                         uint32_t b0, uint32_t b1) {
    asm volatile(
        "mma.sync.aligned.m16n8k16.row.col.f32.f16.f16.f32 "
        "{%0,%1,%2,%3}, {%4,%5,%6,%7}, {%8,%9}, {%0,%1,%2,%3};"
        : "+f"(c[0]), "+f"(c[1]), "+f"(c[2]), "+f"(c[3])
        : "r"(a[0]), "r"(a[1]), "r"(a[2]), "r"(a[3]), "r"(b0), "r"(b1));
}

__device__ __forceinline__ void cp_async16(uint32_t dst, const void* src) {
    asm volatile("cp.async.cg.shared.global [%0], [%1], 16;"
                 :: "r"(dst), "l"(src) : "memory");
}
#define CP_COMMIT() asm volatile("cp.async.commit_group;" ::: "memory")
#define CP_WAIT(n)  asm volatile("cp.async.wait_group %0;" :: "n"(n) : "memory")

// ---------------------------------------------------------------------------
// Setup: block k simulates basis state |k>; writes the 3 Karatsuba weights.
// ---------------------------------------------------------------------------
__global__ void build_weights_kernel(const float* __restrict__ params) {
    __shared__ float2 st[256];
    __shared__ float g[NLAYERS * NQ][8];
    int k = blockIdx.x;
    int t = threadIdx.x;

    if (t < NLAYERS * NQ) {
        const float* pr = params + t * 3;
        float hx = 0.5f * pr[0], hy = 0.5f * pr[1], hz = 0.5f * pr[2];
        float cx = cosf(hx), sx = sinf(hx);
        float cy = cosf(hy), sy = sinf(hy);
        float cz = cosf(hz), sz = sinf(hz);
        float m00r =  cy * cx, m00i =  sy * sx;
        float m01r = -sy * cx, m01i = -cy * sx;
        float m10r =  sy * cx, m10i = -cy * sx;
        float m11r =  cy * cx, m11i = -sy * sx;
        g[t][0] = cz * m00r + sz * m00i;  g[t][1] = cz * m00i - sz * m00r;
        g[t][2] = cz * m01r + sz * m01i;  g[t][3] = cz * m01i - sz * m01r;
        g[t][4] = cz * m10r - sz * m10i;  g[t][5] = cz * m10i + sz * m10r;
        g[t][6] = cz * m11r - sz * m11i;  g[t][7] = cz * m11i + sz * m11r;
    }
    st[t] = make_float2(t == k ? 1.0f : 0.0f, 0.0f);
    __syncthreads();

    for (int l = 0; l < NLAYERS; l++) {
        for (int q = 0; q < NQ; q++) {
            const float* u = g[l * NQ + q];
            float u00r = u[0], u00i = u[1], u01r = u[2], u01i = u[3];
            float u10r = u[4], u10i = u[5], u11r = u[6], u11i = u[7];
            int p = 7 - q;  // qubit 0 = MSB of flat index
            if (t < 128) {
                int lo = t & ((1 << p) - 1);
                int i0 = ((t >> p) << (p + 1)) | lo;
                int i1 = i0 | (1 << p);
                float2 a0 = st[i0], a1 = st[i1];
                float2 n0, n1;
                n0.x = u00r*a0.x - u00i*a0.y + u01r*a1.x - u01i*a1.y;
                n0.y = u00r*a0.y + u00i*a0.x + u01r*a1.y + u01i*a1.x;
                n1.x = u10r*a0.x - u10i*a0.y + u11r*a1.x - u11i*a1.y;
                n1.y = u10r*a0.y + u10i*a0.x + u11r*a1.y + u11i*a1.x;
                st[i0] = n0;
                st[i1] = n1;
            }
            __syncthreads();
        }
        for (int q = 0; q < NQ; q++) {
            int pc = 7 - q;
            int pt = 7 - ((q + 1) & 7);
            if (((t >> pc) & 1) == 1 && ((t >> pt) & 1) == 0) {
                int j = t | (1 << pt);
                float2 tmp = st[t];
                st[t] = st[j];
                st[j] = tmp;
            }
            __syncthreads();
        }
    }
    if (t < 128) {
        float re = st[t].x, im = st[t].y;
        Wg_global[0 * 32768 + t * 256 + k] = __float2half_rn(re);
        Wg_global[1 * 32768 + t * 256 + k] = __float2half_rn(im - re);
        Wg_global[2 * 32768 + t * 256 + k] = __float2half_rn(re + im);
    }
}

// ---------------------------------------------------------------------------
// GEMM: CTA = 128 rows x 128 complex cols, 256 threads = 8 warps,
// warp grid 2(M) x 4(N), warp tile 64 x 32 x 3 planes. K = 256 in 4 chunks
// of 64. A operands {Sr, Si, Sr+Si} converted fp32->fp16 on the fly,
// group-interleaved into the compute; B 3x16KB per chunk via cp.async ring.
// SMEM: A: stage(2) x 48KB at 0 (op x 16KB inside);
//       B: stage(2) x 48KB at 96KB;  red[128] at 192KB.
// ---------------------------------------------------------------------------
static constexpr uint32_t ST_BYTES = 48 * 1024;   // per stage (3 ops x 16KB)
static constexpr uint32_t OFF_B    = 96 * 1024;
static constexpr uint32_t RED_OFF  = 192 * 1024;
static constexpr uint32_t DYN_SMEM = 192 * 1024 + 512 + 1024;

__global__ void __launch_bounds__(256, 1)
qmm_kernel(const float* __restrict__ sre, const float* __restrict__ sim,
           float* __restrict__ out) {
    extern __shared__ char smem_raw[];
    uint32_t base  = smem_u32(smem_raw);
    uint32_t abase = (base + 1023u) & ~1023u;
    char* a = smem_raw + (abase - base);
    float* red = (float*)(a + RED_OFF);

    const int tid  = threadIdx.x;
    const int wid  = tid >> 5;
    const int lane = tid & 31;
    const int wm   = wid >> 2;  // 0..1 : rows wm*64..+63
    const int wn   = wid & 3;   // 0..3 : complex cols wn*32..+31

    // ldmatrix per-lane geometry
    const int r  = lane & 7;
    const int q  = lane >> 3;
    const uint32_t xorv = (uint32_t)r << 4;
    const uint32_t ch16 = (uint32_t)(q >> 1) << 4;
    const int rl = ((q & 1) << 3) + r;

    uint32_t aRow[4], bRow[2];
    #pragma unroll
    for (int mf = 0; mf < 4; mf++)
        aRow[mf] = abase + (uint32_t)(wm * 64 + mf * 16 + rl) * 128;
    #pragma unroll
    for (int nb = 0; nb < 2; nb++)
        bRow[nb] = abase + OFF_B + (uint32_t)(wn * 32 + nb * 16 + rl) * 128;

    const long tileBase = (long)blockIdx.x * 128;

    // acc[plane][mf][nf][i]
    float acc[3][4][4][4];
    #pragma unroll
    for (int p = 0; p < 3; p++)
        #pragma unroll
        for (int mf = 0; mf < 4; mf++)
            #pragma unroll
            for (int nf = 0; nf < 4; nf++)
                #pragma unroll
                for (int i = 0; i < 4; i++) acc[p][mf][nf][i] = 0.0f;

    // A group: 32 rows x 16 float4 per operand; 256 thr -> 2 per op.
    float4 sr4[2], si4[2];

    auto ldgA = [&](int c, int g) {
        int kb = c * 64;
        #pragma unroll
        for (int j = 0; j < 2; j++) {
            int i = tid + j * 256;
            int row = g * 32 + (i >> 4), f4 = i & 15;
            const float* pr = sre + (tileBase + row) * 256 + kb + f4 * 4;
            const float* pi = sim + (tileBase + row) * 256 + kb + f4 * 4;
            sr4[j] = *(const float4*)pr;
            si4[j] = *(const float4*)pi;
        }
    };
    auto stsA = [&](int c, int g) {
        uint32_t stg = (uint32_t)(c & 1) * ST_BYTES;
        #pragma unroll
        for (int j = 0; j < 2; j++) {
            int i = tid + j * 256;
            int row = g * 32 + (i >> 4), f4 = i & 15;
            uint32_t byte = (uint32_t)row * 128 +
                            (((uint32_t)f4 * 8) ^ (((uint32_t)row & 7) << 4));
            float4 s = sr4[j], m = si4[j];
            __half2 r0 = __floats2half2_rn(s.x, s.y);
            __half2 r1 = __floats2half2_rn(s.z, s.w);
            __half2 i0 = __floats2half2_rn(m.x, m.y);
            __half2 i1 = __floats2half2_rn(m.z, m.w);
            __half2 u0 = __floats2half2_rn(s.x + m.x, s.y + m.y);
            __half2 u1 = __floats2half2_rn(s.z + m.z, s.w + m.w);
            uint2 v;
            v.x = *(const uint32_t*)&r0; v.y = *(const uint32_t*)&r1;
            *(uint2*)(a + stg + byte) = v;                    // op0 = Sr
            v.x = *(const uint32_t*)&i0; v.y = *(const uint32_t*)&i1;
            *(uint2*)(a + stg + 16384 + byte) = v;            // op1 = Si
            v.x = *(const uint32_t*)&u0; v.y = *(const uint32_t*)&u1;
            *(uint2*)(a + stg + 32768 + byte) = v;            // op2 = Sr+Si
        }
    };
    auto issueB = [&](int c) {
        uint32_t sb = abase + OFF_B + (uint32_t)(c & 1) * ST_BYTES;
        #pragma unroll
        for (int it = 0; it < 12; it++) {
            int i = tid + it * 256;
            int o = i >> 10;
            int j = i & 1023;
            int n = j >> 3, seg = j & 7;
            uint32_t dst = sb + (uint32_t)o * 16384u + (uint32_t)n * 128 +
                           (((uint32_t)seg * 16) ^ (((uint32_t)n & 7) << 4));
            cp_async16(dst, Wg_global + o * 32768 + n * 256 + c * 64 + seg * 8);
        }
    };
    // plane p: A operand {2,0,1}[p], B operand p
    auto compute_ks = [&](int c, int ks) {
        uint32_t cx = (((uint32_t)ks * 32) | ch16) ^ xorv;
        uint32_t stg = (uint32_t)(c & 1) * ST_BYTES;
        const int aOp[3] = {2, 0, 1};
        #pragma unroll
        for (int p = 0; p < 3; p++) {
            uint32_t af[4][4];
            #pragma unroll
            for (int mf = 0; mf < 4; mf++)
                ldmatrix_x4(af[mf], aRow[mf] + stg + (uint32_t)aOp[p] * 16384u + cx);
            uint32_t bf[2][4];
            #pragma unroll
            for (int nb = 0; nb < 2; nb++)
                ldmatrix_x4(bf[nb], bRow[nb] + stg + (uint32_t)p * 16384u + cx);
            #pragma unroll
            for (int mf = 0; mf < 4; mf++)
                #pragma unroll
                for (int nf = 0; nf < 4; nf++) {
                    int nb = nf >> 1, sub = nf & 1;
                    mma16816(acc[p][mf][nf], af[mf], bf[nb][sub], bf[nb][sub + 2]);
                }
        }
    };

    // ---- prologue: B(0), B(1) async; A(0) converted into stage 0 ----
    issueB(0);
    CP_COMMIT();
    issueB(1);
    CP_COMMIT();
    #pragma unroll
    for (int g = 0; g < 4; g++) { ldgA(0, g); stsA(0, g); }

    // ---- mainloop: 4 chunks of K=64 ----
    for (int c = 0; c < 4; c++) {
        CP_WAIT(1);          // B(c) complete
        __syncthreads();     // B(c) + A(c) visible to all warps

        if (c < 3) ldgA(c + 1, 0);
        compute_ks(c, 0);
        if (c < 3) { stsA(c + 1, 0); ldgA(c + 1, 1); }
        compute_ks(c, 1);
        if (c < 3) { stsA(c + 1, 1); ldgA(c + 1, 2); }
        compute_ks(c, 2);
        if (c < 3) { stsA(c + 1, 2); ldgA(c + 1, 3); }
        compute_ks(c, 3);
        if (c < 3) stsA(c + 1, 3);

        __syncthreads();     // all warps done with B stage (c&1)
        if (c < 2) issueB(c + 2);
        CP_COMMIT();         // uniform group count (empty commits ok)
    }

    // ---- epilogue: Re = k1-k3, Im = k1+k2; out[m] = sum_n Re^2+Im^2 ----
    if (tid < 128) red[tid] = 0.0f;
    __syncthreads();

    #pragma unroll
    for (int mf = 0; mf < 4; mf++) {
        float s_lo = 0.0f, s_hi = 0.0f;
        #pragma unroll
        for (int nf = 0; nf < 4; nf++) {
            #pragma unroll
            for (int i = 0; i < 4; i++) {
                float k1 = acc[0][mf][nf][i];
                float k2 = acc[1][mf][nf][i];
                float k3 = acc[2][mf][nf][i];
                float re = k1 - k3;
                float im = k1 + k2;
                float v = fmaf(re, re, im * im);
                if (i < 2) s_lo += v; else s_hi += v;
            }
        }
        s_lo += __shfl_xor_sync(0xFFFFFFFF, s_lo, 1);
        s_lo += __shfl_xor_sync(0xFFFFFFFF, s_lo, 2);
        s_hi += __shfl_xor_sync(0xFFFFFFFF, s_hi, 1);
        s_hi += __shfl_xor_sync(0xFFFFFFFF, s_hi, 2);
        if ((lane & 3) == 0) {
            int row = wm * 64 + mf * 16 + (lane >> 2);
            atomicAdd(red + row, s_lo);
            atomicAdd(red + row + 8, s_hi);
        }
    }
    __syncthreads();
    if (tid < 128) out[tileBase + tid] = red[tid];
}

// ---------------------------------------------------------------------------
extern "C" void kernel_launch(void* const* d_in, const int* in_sizes, int n_in,
                              void* d_out, int out_size) {
    const float* params = (const float*)d_in[0];
    const float* sre    = (const float*)d_in[1];
    const float* sim    = (const float*)d_in[2];
    float* out = (float*)d_out;

    cudaFuncSetAttribute(qmm_kernel, cudaFuncAttributeMaxDynamicSharedMemorySize,
                         DYN_SMEM);

    build_weights_kernel<<<256, 256>>>(params);
    qmm_kernel<<<1024, 256, DYN_SMEM>>>(sre, sim, out);
}